// round 8
// baseline (speedup 1.0000x reference)
#include <cuda_runtime.h>
#include <mma.h>
#include <cstdint>
#include <cstddef>
using namespace nvcuda;

#define TS    512
#define BATCH 128
#define D     512
#define H     512
#define NG3   1536
#define MT    (TS*BATCH)
#define NGC   128
#define BH_   ((size_t)BATCH*H)
#define TBH_  ((size_t)TS*BATCH*H)
#define LDW   516
#define LDO   52

// rec smem float offsets
#define SM_W   0
#define SM_A   (48*LDW)                 // 24768
#define SM_O   (SM_A + 32*LDW)          // 41280
#define SM_F   (SM_O + 4*32*LDO)        // 47936
#define SM_TOT (SM_F + 32)              // 47968
#define REC_SMEM (SM_TOT*4)             // 191872 B

// gemm_x smem: 3 stages x (256 rows x 36 floats)
#define GXS        3
#define GX_STAGE_F (256*36)
#define GX_SMEM    (GXS*GX_STAGE_F*4)   // 110592 B

__device__ float    g_Gx[(size_t)MT*NG3];
__device__ float    g_Fx[(size_t)MT*2];
__device__ float    g_Xr[(size_t)MT*D];
__device__ float    g_Wx[(size_t)NG3*D];
__device__ float    g_Whh[(size_t)NG3*H];
__device__ float    g_bias[NG3];
__device__ unsigned g_flagw[(size_t)TS*NGC];

__device__ __forceinline__ float t32(float x){ return wmma::__float_to_tf32(x); }
__device__ __forceinline__ float sigm(float x){ return 1.f/(1.f+expf(-x)); }
__device__ __forceinline__ void cpa16(uint32_t dst, const void* src){
    asm volatile("cp.async.ca.shared.global [%0], [%1], 16;\n" :: "r"(dst), "l"(src));
}
__device__ __forceinline__ void cpacg16(uint32_t dst, const void* src){
    asm volatile("cp.async.cg.shared.global [%0], [%1], 16;\n" :: "r"(dst), "l"(src));
}
__device__ __forceinline__ unsigned ld_acq(const unsigned* p){
    unsigned v; asm volatile("ld.global.acquire.gpu.u32 %0, [%1];" : "=r"(v) : "l"(p) : "memory"); return v;
}
__device__ __forceinline__ void st_rel(unsigned* p, unsigned v){
    asm volatile("st.global.release.gpu.u32 [%0], %1;" :: "l"(p), "r"(v) : "memory");
}

// ---------- prep: pack weights (tf32-rounded) + zero flags ----------
__global__ void prep_kernel(const float* __restrict__ Wi, const float* __restrict__ Wu,
                            const float* __restrict__ Wo, const float* __restrict__ bi,
                            const float* __restrict__ bu, const float* __restrict__ bo) {
    int n = blockIdx.x;
    if (n < NG3) {
        int g = n >> 9, j = n & 511;
        const float* W = (g==0) ? Wi : (g==1 ? Wu : Wo);
        const float* s = W + (size_t)j*(D+H);
        for (int k = threadIdx.x; k < D; k += blockDim.x) {
            g_Wx [(size_t)n*D + k] = t32(s[k]);
            g_Whh[(size_t)n*H + k] = t32(s[D+k]);
        }
        if (threadIdx.x == 0) g_bias[n] = (g==0 ? bi : (g==1 ? bu : bo))[j];
    } else {
        int base = (n - NG3) * 8192;
        for (int k = threadIdx.x; k < 8192; k += blockDim.x) g_flagw[base + k] = 0u;
    }
}

// ---------- round X to tf32 once ----------
__global__ void prepx_kernel(const float* __restrict__ X) {
    size_t i = ((size_t)blockIdx.x*256 + threadIdx.x)*4;
    float4 v = *(const float4*)(X + i);
    float4 o; o.x=t32(v.x); o.y=t32(v.y); o.z=t32(v.z); o.w=t32(v.w);
    *(float4*)(g_Xr + i) = o;
}

// ---------- x-part of forget logits (fp32 exact) ----------
__global__ void fx_kernel(const float* __restrict__ X, const float* __restrict__ Wf,
                          const float* __restrict__ bf) {
    int m = blockIdx.x*8 + (threadIdx.x>>5);
    int lane = threadIdx.x & 31;
    const float* x = X + (size_t)m*D;
    float s0 = 0.f, s1 = 0.f;
    #pragma unroll 4
    for (int k = lane; k < D; k += 32) {
        float xv = x[k];
        s0 += xv * __ldg(&Wf[k]);
        s1 += xv * __ldg(&Wf[1024+k]);
    }
    #pragma unroll
    for (int o = 16; o; o >>= 1) {
        s0 += __shfl_xor_sync(~0u, s0, o);
        s1 += __shfl_xor_sync(~0u, s1, o);
    }
    if (lane == 0) {
        g_Fx[(size_t)m*2+0] = s0 + __ldg(&bf[0]);
        g_Fx[(size_t)m*2+1] = s1 + __ldg(&bf[1]);
    }
}

// ---------- big parallel GEMM: Gx = Xr @ Wx.T (tf32 WMMA, cp.async pipeline) ----------
__global__ void __launch_bounds__(256) gemm_x() {
    extern __shared__ float sb[];
    uint32_t sbase = (uint32_t)__cvta_generic_to_shared(sb);
    int tid = threadIdx.x, wid = tid>>5;
    int n0 = blockIdx.x*128, m0 = blockIdx.y*128;
    int wm = wid>>1, wn = wid&1;
    int lr = tid>>3, lc = (tid&7)*4;

    wmma::fragment<wmma::accumulator,16,16,8,float> acc[2][4];
    #pragma unroll
    for (int i=0;i<2;i++)
        #pragma unroll
        for (int j=0;j<4;j++) wmma::fill_fragment(acc[i][j], 0.f);

    auto load_chunk = [&](int s, int kc) {
        const float* As = g_Xr + (size_t)m0*D + kc*32;
        const float* Bsrc = g_Wx + (size_t)n0*D + kc*32;
        uint32_t ds = sbase + (uint32_t)s*GX_STAGE_F*4;
        #pragma unroll
        for (int u = 0; u < 4; u++) {
            int rr = lr + u*32;
            cpa16(ds + (uint32_t)(rr*36+lc)*4,       As   + (size_t)rr*D + lc);
            cpa16(ds + (uint32_t)((128+rr)*36+lc)*4, Bsrc + (size_t)rr*D + lc);
        }
        asm volatile("cp.async.commit_group;\n");
    };

    load_chunk(0,0); load_chunk(1,1);
    for (int kc = 0; kc < 16; kc++) {
        asm volatile("cp.async.wait_group 1;\n");
        __syncthreads();
        if (kc+2 < 16) load_chunk((kc+2)%GXS, kc+2);
        else asm volatile("cp.async.commit_group;\n");
        float* As = sb + (kc%GXS)*GX_STAGE_F;
        float* Bs = As + 128*36;
        #pragma unroll
        for (int kk = 0; kk < 4; kk++) {
            wmma::fragment<wmma::matrix_a,16,16,8,wmma::precision::tf32,wmma::row_major> a0,a1;
            wmma::fragment<wmma::matrix_b,16,16,8,wmma::precision::tf32,wmma::col_major> b0,b1,b2,b3;
            wmma::load_matrix_sync(a0, &As[(wm*32+ 0)*36 + kk*8], 36);
            wmma::load_matrix_sync(a1, &As[(wm*32+16)*36 + kk*8], 36);
            wmma::load_matrix_sync(b0, &Bs[(wn*64+ 0)*36 + kk*8], 36);
            wmma::load_matrix_sync(b1, &Bs[(wn*64+16)*36 + kk*8], 36);
            wmma::load_matrix_sync(b2, &Bs[(wn*64+32)*36 + kk*8], 36);
            wmma::load_matrix_sync(b3, &Bs[(wn*64+48)*36 + kk*8], 36);
            wmma::mma_sync(acc[0][0], a0, b0, acc[0][0]);
            wmma::mma_sync(acc[0][1], a0, b1, acc[0][1]);
            wmma::mma_sync(acc[0][2], a0, b2, acc[0][2]);
            wmma::mma_sync(acc[0][3], a0, b3, acc[0][3]);
            wmma::mma_sync(acc[1][0], a1, b0, acc[1][0]);
            wmma::mma_sync(acc[1][1], a1, b1, acc[1][1]);
            wmma::mma_sync(acc[1][2], a1, b2, acc[1][2]);
            wmma::mma_sync(acc[1][3], a1, b3, acc[1][3]);
        }
    }
    #pragma unroll
    for (int i=0;i<2;i++)
        #pragma unroll
        for (int j=0;j<4;j++)
            wmma::store_matrix_sync(g_Gx + (size_t)(m0+wm*32+i*16)*NG3 + n0+wn*64+j*16,
                                    acc[i][j], NG3, wmma::mem_row_major);
}

// ---------- persistent recurrent kernel: 128 CTAs x 512 threads ----------
__global__ void __launch_bounds__(512,1) rec_kernel(
        float* __restrict__ out, const float* __restrict__ Wf,
        const float* __restrict__ Ws1, const float* __restrict__ bs1,
        const float* __restrict__ Ws2, const float* __restrict__ bs2,
        long long out_size) {
    extern __shared__ float sm[];
    float* sW = sm + SM_W;
    float* sA = sm + SM_A;
    float* sO = sm + SM_O;
    float* sF = sm + SM_F;
    uint32_t sAb = (uint32_t)__cvta_generic_to_shared(sA);
    int tid = threadIdx.x, wid = tid>>5, lane = tid&31;
    bool tail = out_size >= (long long)(TBH_ + 2*BH_);

    int rb = blockIdx.x >> 5, jt = blockIdx.x & 31;
    int row0 = rb*32, j0 = jt*16;

    // recurrent weights (48 rows x 512) -> smem, once
    for (int idx = tid; idx < 48*512; idx += 512) {
        int row = idx >> 9, k = idx & 511;
        sW[row*LDW + k] = g_Whh[(size_t)((row>>4)*512 + j0 + (row&15))*H + k];
    }

    // epilogue slot: 1 output per thread
    int rp = tid>>4, jp = tid&15;
    int bq = row0+rp, jj = j0+jp;
    float bI = g_bias[jj], bU = g_bias[512+jj], bO = g_bias[1024+jj];
    float cst = 0.f;

    // GEMM roles: warps 0..11 -> wc (gate) in {0,1,2}, kq in {0..3}
    int wc = wid >> 2, kq = wid & 3;
    // f roles: warps 12..15 -> 8 rows each; per-lane weight slices in regs
    int fw = wid - 12, rbase = fw*8;
    float wA[16], wB[16];
    float w1v[8], vb1[4], w2d[4], db = 0.f;
    if (wid >= 12) {
        #pragma unroll
        for (int i = 0; i < 4; i++) {
            float4 a = *(const float4*)(Wf + 512  + i*128 + lane*4);
            float4 b = *(const float4*)(Wf + 1536 + i*128 + lane*4);
            wA[i*4]=a.x; wA[i*4+1]=a.y; wA[i*4+2]=a.z; wA[i*4+3]=a.w;
            wB[i*4]=b.x; wB[i*4+1]=b.y; wB[i*4+2]=b.z; wB[i*4+3]=b.w;
        }
        #pragma unroll
        for (int i=0;i<8;i++) w1v[i] = Ws1[i];
        #pragma unroll
        for (int i=0;i<4;i++) { vb1[i] = bs1[i]; w2d[i] = Ws2[i] - Ws2[4+i]; }
        db = bs2[0] - bs2[1];
    }
    __syncthreads();

    // preload B fragments into registers (persist across all 512 steps)
    wmma::fragment<wmma::matrix_b,16,16,8,wmma::precision::tf32,wmma::col_major> bfr[16];
    if (wid < 12) {
        #pragma unroll
        for (int q = 0; q < 16; q++)
            wmma::load_matrix_sync(bfr[q], &sW[(wc*16)*LDW + (kq*16+q)*8], LDW);
    }
    __syncthreads();

    for (int t = 0; t < TS; t++) {
        // prefetch x-parts (no recurrent dependency; DRAM latency hidden under poll)
        size_t gb = ((size_t)t*BATCH + bq)*NG3;
        float gi = __ldg(&g_Gx[gb+jj]);
        float gu = __ldg(&g_Gx[gb+512+jj]);
        float go = __ldg(&g_Gx[gb+1024+jj]);
        float fx0 = 0.f, fx1 = 0.f;
        if (wid >= 12 && lane < 8) {
            const float* fp = &g_Fx[((size_t)t*BATCH + row0 + rbase + lane)*2];
            fx0 = __ldg(fp); fx1 = __ldg(fp+1);
        }

        if (t > 0) {
            // every warp polls independently: lane l watches producer (rb, l)
            const unsigned* flp = &g_flagw[(size_t)(t-1)*NGC + rb*32 + lane];
            unsigned v = ld_acq(flp);
            while (__ballot_sync(~0u, v == 0u)) { if (v == 0u) v = ld_acq(flp); }
        }

        if (wid < 12) {
            // stage h[t-1] (already tf32-rounded at producer) via cp.async
            if (t > 0) {
                const float* hb = out + (size_t)(t-1)*BH_ + (size_t)row0*H;
                for (int i = tid; i < 4096; i += 384) {
                    int r = i >> 7, c = i & 127;
                    cpacg16(sAb + (uint32_t)(r*LDW + c*4)*4, hb + (size_t)r*H + c*4);
                }
                asm volatile("cp.async.commit_group;\n");
                asm volatile("cp.async.wait_group 0;\n" ::: "memory");
            }
            asm volatile("bar.sync 1, 384;" ::: "memory");

            wmma::fragment<wmma::accumulator,16,16,8,float> acc0, acc1;
            wmma::fill_fragment(acc0, 0.f);
            wmma::fill_fragment(acc1, 0.f);
            if (t > 0) {
                #pragma unroll
                for (int q = 0; q < 16; q++) {
                    int kk = kq*16 + q;
                    wmma::fragment<wmma::matrix_a,16,16,8,wmma::precision::tf32,wmma::row_major> a0, a1;
                    wmma::load_matrix_sync(a0, &sA[kk*8], LDW);
                    wmma::load_matrix_sync(a1, &sA[16*LDW + kk*8], LDW);
                    wmma::mma_sync(acc0, a0, bfr[q], acc0);
                    wmma::mma_sync(acc1, a1, bfr[q], acc1);
                }
            }
            wmma::store_matrix_sync(&sO[(kq*32+ 0)*LDO + wc*16], acc0, LDO, wmma::mem_row_major);
            wmma::store_matrix_sync(&sO[(kq*32+16)*LDO + wc*16], acc1, LDO, wmma::mem_row_major);
        } else {
            // forget gate: 8 rows per warp, h from global (L2), weights in regs
            float p0[8], p1[8];
            #pragma unroll
            for (int r=0;r<8;r++){ p0[r]=0.f; p1[r]=0.f; }
            if (t > 0) {
                const float* hb = out + (size_t)(t-1)*BH_ + (size_t)(row0+rbase)*H;
                #pragma unroll
                for (int r = 0; r < 8; r++) {
                    float s0=0.f, s1=0.f;
                    #pragma unroll
                    for (int i = 0; i < 4; i++) {
                        float4 v = *(const float4*)(hb + (size_t)r*H + i*128 + lane*4);
                        s0 += v.x*wA[i*4]+v.y*wA[i*4+1]+v.z*wA[i*4+2]+v.w*wA[i*4+3];
                        s1 += v.x*wB[i*4]+v.y*wB[i*4+1]+v.z*wB[i*4+2]+v.w*wB[i*4+3];
                    }
                    p0[r]=s0; p1[r]=s1;
                }
            }
            #pragma unroll
            for (int r = 0; r < 8; r++) {
                #pragma unroll
                for (int o = 16; o; o >>= 1) {
                    p0[r] += __shfl_xor_sync(~0u, p0[r], o);
                    p1[r] += __shfl_xor_sync(~0u, p1[r], o);
                }
            }
            if (lane < 8) {
                float a0=0.f, a1=0.f;
                #pragma unroll
                for (int r = 0; r < 8; r++) if (lane == r) { a0 = p0[r]; a1 = p1[r]; }
                float fl0 = a0 + fx0, fl1 = a1 + fx1;
                float h0 = tanhf(w1v[0]*fl0 + w1v[1]*fl1 + vb1[0]);
                float h1 = tanhf(w1v[2]*fl0 + w1v[3]*fl1 + vb1[1]);
                float h2 = tanhf(w1v[4]*fl0 + w1v[5]*fl1 + vb1[2]);
                float h3 = tanhf(w1v[6]*fl0 + w1v[7]*fl1 + vb1[3]);
                float dl = w2d[0]*h0 + w2d[1]*h1 + w2d[2]*h2 + w2d[3]*h3 + db;
                sF[rbase + lane] = sigm(dl);
            }
        }
        __syncthreads();

        // epilogue: sum 4 K-quarter partials + x-part + bias; LSTM update (1 out/thread)
        float fv = sF[rp];
        float pi = sO[(  rp)*LDO + jp]      + sO[(32+rp)*LDO + jp]
                 + sO[(64+rp)*LDO + jp]     + sO[(96+rp)*LDO + jp]      + gi + bI;
        float pu = sO[(  rp)*LDO + 16+jp]   + sO[(32+rp)*LDO + 16+jp]
                 + sO[(64+rp)*LDO + 16+jp]  + sO[(96+rp)*LDO + 16+jp]   + gu + bU;
        float po = sO[(  rp)*LDO + 32+jp]   + sO[(32+rp)*LDO + 32+jp]
                 + sO[(64+rp)*LDO + 32+jp]  + sO[(96+rp)*LDO + 32+jp]   + go + bO;
        cst = fv*cst + sigm(pi)*tanhf(pu);
        float hv = t32(sigm(po)*tanhf(cst));   // round at production: consumers' MMA truncation is exact
        __stcg(&out[(size_t)t*BH_ + (size_t)bq*H + jj], hv);
        if (t == TS-1 && tail) {
            out[TBH_ + (size_t)bq*H + jj] = hv;
            out[TBH_ + BH_ + (size_t)bq*H + jj] = cst;
        }
        __syncthreads();
        if (tid == 0) st_rel(&g_flagw[(size_t)t*NGC + blockIdx.x], 1u);
    }
}

extern "C" void kernel_launch(void* const* d_in, const int* in_sizes, int n_in,
                              void* d_out, int out_size) {
    const float* X   = (const float*)d_in[0];
    const float* Wf  = (const float*)d_in[1];
    const float* bf  = (const float*)d_in[2];
    const float* Wi  = (const float*)d_in[3];
    const float* bi  = (const float*)d_in[4];
    const float* Wu  = (const float*)d_in[5];
    const float* bu  = (const float*)d_in[6];
    const float* Wo  = (const float*)d_in[7];
    const float* bo  = (const float*)d_in[8];
    const float* Ws1 = (const float*)d_in[9];
    const float* bs1 = (const float*)d_in[10];
    const float* Ws2 = (const float*)d_in[11];
    const float* bs2 = (const float*)d_in[12];
    float* out = (float*)d_out;

    cudaFuncSetAttribute(rec_kernel, cudaFuncAttributeMaxDynamicSharedMemorySize, REC_SMEM);
    cudaFuncSetAttribute(gemm_x,     cudaFuncAttributeMaxDynamicSharedMemorySize, GX_SMEM);

    prep_kernel<<<NG3+8, 128>>>(Wi, Wu, Wo, bi, bu, bo);
    prepx_kernel<<<MT*D/1024, 256>>>(X);
    fx_kernel<<<MT/8, 256>>>(X, Wf, bf);
    dim3 g(NG3/128, MT/128);
    gemm_x<<<g, 256, GX_SMEM>>>();
    rec_kernel<<<NGC, 512, REC_SMEM>>>(out, Wf, Ws1, bs1, Ws2, bs2, (long long)out_size);
}

// round 9
// speedup vs baseline: 1.2975x; 1.2975x over previous
#include <cuda_runtime.h>
#include <mma.h>
#include <cstdint>
#include <cstddef>
using namespace nvcuda;

#define TS    512
#define BATCH 128
#define D     512
#define H     512
#define NG3   1536
#define MT    (TS*BATCH)
#define NGC   128
#define BH_   ((size_t)BATCH*H)
#define TBH_  ((size_t)TS*BATCH*H)
#define LDW   516
#define LDO   52

// rec smem float offsets
#define SM_W    0
#define SM_A    (48*LDW)                 // 24768
#define SM_O    (SM_A + 32*LDW)          // 41280
#define SM_F    (SM_O + 4*32*LDO)        // 47936
#define SM_WF   (SM_F + 32)              // 47968
#define SM_GX   (SM_WF + 1024)           // 48992
#define SM_FX   (SM_GX + 1536)           // 50528
#define SM_B    (SM_FX + 64)             // 50592
#define SM_MLP  (SM_B + 48)              // 50640
#define SM_TOT  (SM_MLP + 20)            // 50660
#define REC_SMEM (SM_TOT*4)              // 202640 B

// gemm_x smem: 3 stages x (256 rows x 36 floats)
#define GXS        3
#define GX_STAGE_F (256*36)
#define GX_SMEM    (GXS*GX_STAGE_F*4)

__device__ float    g_Gx[(size_t)MT*NG3];
__device__ float    g_Fx[(size_t)MT*2];
__device__ float    g_Xr[(size_t)MT*D];
__device__ float    g_Wx[(size_t)NG3*D];
__device__ float    g_Whh[(size_t)NG3*H];
__device__ float    g_bias[NG3];
__device__ unsigned g_flagw[(size_t)TS*NGC];

__device__ __forceinline__ float t32(float x){ return wmma::__float_to_tf32(x); }
__device__ __forceinline__ float sigm(float x){ return __fdividef(1.f, 1.f + __expf(-x)); }
__device__ __forceinline__ void cpa16(uint32_t dst, const void* src){
    asm volatile("cp.async.ca.shared.global [%0], [%1], 16;\n" :: "r"(dst), "l"(src));
}
__device__ __forceinline__ void cpa8(uint32_t dst, const void* src){
    asm volatile("cp.async.ca.shared.global [%0], [%1], 8;\n" :: "r"(dst), "l"(src));
}
__device__ __forceinline__ void cpa4(uint32_t dst, const void* src){
    asm volatile("cp.async.ca.shared.global [%0], [%1], 4;\n" :: "r"(dst), "l"(src));
}

// ---------- prep: pack weights (tf32-rounded) + zero flags ----------
__global__ void prep_kernel(const float* __restrict__ Wi, const float* __restrict__ Wu,
                            const float* __restrict__ Wo, const float* __restrict__ bi,
                            const float* __restrict__ bu, const float* __restrict__ bo) {
    int n = blockIdx.x;
    if (n < NG3) {
        int g = n >> 9, j = n & 511;
        const float* W = (g==0) ? Wi : (g==1 ? Wu : Wo);
        const float* s = W + (size_t)j*(D+H);
        for (int k = threadIdx.x; k < D; k += blockDim.x) {
            g_Wx [(size_t)n*D + k] = t32(s[k]);
            g_Whh[(size_t)n*H + k] = t32(s[D+k]);
        }
        if (threadIdx.x == 0) g_bias[n] = (g==0 ? bi : (g==1 ? bu : bo))[j];
    } else {
        int base = (n - NG3) * 8192;
        for (int k = threadIdx.x; k < 8192; k += blockDim.x) g_flagw[base + k] = 0u;
    }
}

// ---------- round X to tf32 once ----------
__global__ void prepx_kernel(const float* __restrict__ X) {
    size_t i = ((size_t)blockIdx.x*256 + threadIdx.x)*4;
    float4 v = *(const float4*)(X + i);
    float4 o; o.x=t32(v.x); o.y=t32(v.y); o.z=t32(v.z); o.w=t32(v.w);
    *(float4*)(g_Xr + i) = o;
}

// ---------- x-part of forget logits (fp32 exact) ----------
__global__ void fx_kernel(const float* __restrict__ X, const float* __restrict__ Wf,
                          const float* __restrict__ bf) {
    int m = blockIdx.x*8 + (threadIdx.x>>5);
    int lane = threadIdx.x & 31;
    const float* x = X + (size_t)m*D;
    float s0 = 0.f, s1 = 0.f;
    #pragma unroll 4
    for (int k = lane; k < D; k += 32) {
        float xv = x[k];
        s0 += xv * __ldg(&Wf[k]);
        s1 += xv * __ldg(&Wf[1024+k]);
    }
    #pragma unroll
    for (int o = 16; o; o >>= 1) {
        s0 += __shfl_xor_sync(~0u, s0, o);
        s1 += __shfl_xor_sync(~0u, s1, o);
    }
    if (lane == 0) {
        g_Fx[(size_t)m*2+0] = s0 + __ldg(&bf[0]);
        g_Fx[(size_t)m*2+1] = s1 + __ldg(&bf[1]);
    }
}

// ---------- big parallel GEMM: Gx = Xr @ Wx.T (tf32 WMMA, cp.async pipeline) ----------
__global__ void __launch_bounds__(256) gemm_x() {
    extern __shared__ float sb[];
    uint32_t sbase = (uint32_t)__cvta_generic_to_shared(sb);
    int tid = threadIdx.x, wid = tid>>5;
    int n0 = blockIdx.x*128, m0 = blockIdx.y*128;
    int wm = wid>>1, wn = wid&1;
    int lr = tid>>3, lc = (tid&7)*4;

    wmma::fragment<wmma::accumulator,16,16,8,float> acc[2][4];
    #pragma unroll
    for (int i=0;i<2;i++)
        #pragma unroll
        for (int j=0;j<4;j++) wmma::fill_fragment(acc[i][j], 0.f);

    auto load_chunk = [&](int s, int kc) {
        const float* As = g_Xr + (size_t)m0*D + kc*32;
        const float* Bsrc = g_Wx + (size_t)n0*D + kc*32;
        uint32_t ds = sbase + (uint32_t)s*GX_STAGE_F*4;
        #pragma unroll
        for (int u = 0; u < 4; u++) {
            int rr = lr + u*32;
            cpa16(ds + (uint32_t)(rr*36+lc)*4,       As   + (size_t)rr*D + lc);
            cpa16(ds + (uint32_t)((128+rr)*36+lc)*4, Bsrc + (size_t)rr*D + lc);
        }
        asm volatile("cp.async.commit_group;\n");
    };

    load_chunk(0,0); load_chunk(1,1);
    for (int kc = 0; kc < 16; kc++) {
        asm volatile("cp.async.wait_group 1;\n");
        __syncthreads();
        if (kc+2 < 16) load_chunk((kc+2)%GXS, kc+2);
        else asm volatile("cp.async.commit_group;\n");
        float* As = sb + (kc%GXS)*GX_STAGE_F;
        float* Bs = As + 128*36;
        #pragma unroll
        for (int kk = 0; kk < 4; kk++) {
            wmma::fragment<wmma::matrix_a,16,16,8,wmma::precision::tf32,wmma::row_major> a0,a1;
            wmma::fragment<wmma::matrix_b,16,16,8,wmma::precision::tf32,wmma::col_major> b0,b1,b2,b3;
            wmma::load_matrix_sync(a0, &As[(wm*32+ 0)*36 + kk*8], 36);
            wmma::load_matrix_sync(a1, &As[(wm*32+16)*36 + kk*8], 36);
            wmma::load_matrix_sync(b0, &Bs[(wn*64+ 0)*36 + kk*8], 36);
            wmma::load_matrix_sync(b1, &Bs[(wn*64+16)*36 + kk*8], 36);
            wmma::load_matrix_sync(b2, &Bs[(wn*64+32)*36 + kk*8], 36);
            wmma::load_matrix_sync(b3, &Bs[(wn*64+48)*36 + kk*8], 36);
            wmma::mma_sync(acc[0][0], a0, b0, acc[0][0]);
            wmma::mma_sync(acc[0][1], a0, b1, acc[0][1]);
            wmma::mma_sync(acc[0][2], a0, b2, acc[0][2]);
            wmma::mma_sync(acc[0][3], a0, b3, acc[0][3]);
            wmma::mma_sync(acc[1][0], a1, b0, acc[1][0]);
            wmma::mma_sync(acc[1][1], a1, b1, acc[1][1]);
            wmma::mma_sync(acc[1][2], a1, b2, acc[1][2]);
            wmma::mma_sync(acc[1][3], a1, b3, acc[1][3]);
        }
    }
    #pragma unroll
    for (int i=0;i<2;i++)
        #pragma unroll
        for (int j=0;j<4;j++)
            wmma::store_matrix_sync(g_Gx + (size_t)(m0+wm*32+i*16)*NG3 + n0+wn*64+j*16,
                                    acc[i][j], NG3, wmma::mem_row_major);
}

// ---------- persistent recurrent kernel: 128 CTAs x 512 threads ----------
__global__ void __launch_bounds__(512,1) rec_kernel(
        float* __restrict__ out, const float* __restrict__ Wf,
        const float* __restrict__ Ws1, const float* __restrict__ bs1,
        const float* __restrict__ Ws2, const float* __restrict__ bs2,
        long long out_size) {
    extern __shared__ float sm[];
    float* sW   = sm + SM_W;
    float* sA   = sm + SM_A;
    float* sO   = sm + SM_O;
    float* sF   = sm + SM_F;
    float* sWf  = sm + SM_WF;
    float* sGX  = sm + SM_GX;
    float* sFX  = sm + SM_FX;
    float* sB   = sm + SM_B;
    float* sMLP = sm + SM_MLP;
    uint32_t sGXb = (uint32_t)__cvta_generic_to_shared(sGX);
    uint32_t sFXb = (uint32_t)__cvta_generic_to_shared(sFX);
    int tid = threadIdx.x, wid = tid>>5, lane = tid&31;
    bool tail = out_size >= (long long)(TBH_ + 2*BH_);

    int rb = blockIdx.x >> 5, jt = blockIdx.x & 31;
    int row0 = rb*32, j0 = jt*16;

    // one-time smem setup
    for (int idx = tid; idx < 48*512; idx += 512) {
        int row = idx >> 9, k = idx & 511;
        sW[row*LDW + k] = g_Whh[(size_t)((row>>4)*512 + j0 + (row&15))*H + k];
    }
    for (int k = tid; k < 512; k += 512) { sWf[k] = Wf[512+k]; sWf[512+k] = Wf[1536+k]; }
    if (tid < 48) sB[tid] = g_bias[(tid>>4)*512 + j0 + (tid&15)];
    if (tid == 0) {
        #pragma unroll
        for (int i=0;i<8;i++) sMLP[i] = Ws1[i];
        #pragma unroll
        for (int i=0;i<4;i++) { sMLP[8+i] = bs1[i]; sMLP[12+i] = Ws2[i] - Ws2[4+i]; }
        sMLP[16] = bs2[0] - bs2[1];
    }

    // epilogue slot: 1 output per thread
    int rp = tid>>4, jp = tid&15;
    int bq = row0+rp, jj = j0+jp;
    float cst = 0.f;

    // GEMM roles: warps 0..11 -> wc (gate) {0,1,2}, kq {0..3}; f roles: warps 12..15
    int wc = wid >> 2, kq = wid & 3;
    int fw = wid - 12, rbase = fw*8;
    __syncthreads();

    // preload B fragments into registers (persist across all 512 steps)
    wmma::fragment<wmma::matrix_b,16,16,8,wmma::precision::tf32,wmma::col_major> bfr[16];
    if (wid < 12) {
        #pragma unroll
        for (int q = 0; q < 16; q++)
            wmma::load_matrix_sync(bfr[q], &sW[(wc*16)*LDW + (kq*16+q)*8], LDW);
    }
    __syncthreads();

    for (int t = 0; t < TS; t++) {
        // A) async prefetch of x-part preactivations (no registers held)
        {
            const float* gsrc = g_Gx + ((size_t)t*BATCH + bq)*NG3 + jj;
            cpa4(sGXb + (uint32_t)tid*4,        gsrc);
            cpa4(sGXb + (uint32_t)(512+tid)*4,  gsrc + 512);
            cpa4(sGXb + (uint32_t)(1024+tid)*4, gsrc + 1024);
            if (wid >= 12 && lane < 8) {
                int r = rbase + lane;
                cpa8(sFXb + (uint32_t)r*8, g_Fx + ((size_t)t*BATCH + row0 + r)*2);
            }
            asm volatile("cp.async.commit_group;\n");
        }

        // B) wait for producers (one warp polls), then stage h[t-1]
        if (t > 0) {
            if (wid == 0) {
                volatile unsigned* fl = &g_flagw[(size_t)(t-1)*NGC + rb*32 + lane];
                while (*fl == 0u) {}
            }
            __syncthreads();
            const float* hb = out + (size_t)(t-1)*BH_;
            #pragma unroll
            for (int u = 0; u < 8; u++) {
                int f4 = tid + u*512;
                int r = f4 >> 7, c4 = f4 & 127;
                float4 v = *(const float4*)(hb + (size_t)(row0+r)*H + c4*4);
                float* d = &sA[r*LDW + c4*4];
                d[0]=t32(v.x); d[1]=t32(v.y); d[2]=t32(v.z); d[3]=t32(v.w);
            }
        }
        __syncthreads();

        if (wid < 12) {
            // gate GEMM: this warp: cols [wc*16,..+16), K-quarter kq
            wmma::fragment<wmma::accumulator,16,16,8,float> acc0, acc1;
            wmma::fill_fragment(acc0, 0.f);
            wmma::fill_fragment(acc1, 0.f);
            if (t > 0) {
                #pragma unroll
                for (int q = 0; q < 16; q++) {
                    int kk = kq*16 + q;
                    wmma::fragment<wmma::matrix_a,16,16,8,wmma::precision::tf32,wmma::row_major> a0, a1;
                    wmma::load_matrix_sync(a0, &sA[kk*8], LDW);
                    wmma::load_matrix_sync(a1, &sA[16*LDW + kk*8], LDW);
                    wmma::mma_sync(acc0, a0, bfr[q], acc0);
                    wmma::mma_sync(acc1, a1, bfr[q], acc1);
                }
            }
            wmma::store_matrix_sync(&sO[(kq*32+ 0)*LDO + wc*16], acc0, LDO, wmma::mem_row_major);
            wmma::store_matrix_sync(&sO[(kq*32+16)*LDO + wc*16], acc1, LDO, wmma::mem_row_major);
        } else {
            // forget gate from staged sA (tf32) — weights loaded per step (short liveness)
            float4 wa0 = *(const float4*)&sWf[      0*128 + lane*4];
            float4 wa1 = *(const float4*)&sWf[      1*128 + lane*4];
            float4 wa2 = *(const float4*)&sWf[      2*128 + lane*4];
            float4 wa3 = *(const float4*)&sWf[      3*128 + lane*4];
            float4 wb0 = *(const float4*)&sWf[512 + 0*128 + lane*4];
            float4 wb1 = *(const float4*)&sWf[512 + 1*128 + lane*4];
            float4 wb2 = *(const float4*)&sWf[512 + 2*128 + lane*4];
            float4 wb3 = *(const float4*)&sWf[512 + 3*128 + lane*4];
            float p0[8], p1[8];
            #pragma unroll
            for (int r=0;r<8;r++){ p0[r]=0.f; p1[r]=0.f; }
            if (t > 0) {
                #pragma unroll
                for (int r = 0; r < 8; r++) {
                    const float* ar = &sA[(rbase+r)*LDW];
                    float4 v0 = *(const float4*)&ar[0*128 + lane*4];
                    float4 v1 = *(const float4*)&ar[1*128 + lane*4];
                    float4 v2 = *(const float4*)&ar[2*128 + lane*4];
                    float4 v3 = *(const float4*)&ar[3*128 + lane*4];
                    p0[r] = v0.x*wa0.x+v0.y*wa0.y+v0.z*wa0.z+v0.w*wa0.w
                          + v1.x*wa1.x+v1.y*wa1.y+v1.z*wa1.z+v1.w*wa1.w
                          + v2.x*wa2.x+v2.y*wa2.y+v2.z*wa2.z+v2.w*wa2.w
                          + v3.x*wa3.x+v3.y*wa3.y+v3.z*wa3.z+v3.w*wa3.w;
                    p1[r] = v0.x*wb0.x+v0.y*wb0.y+v0.z*wb0.z+v0.w*wb0.w
                          + v1.x*wb1.x+v1.y*wb1.y+v1.z*wb1.z+v1.w*wb1.w
                          + v2.x*wb2.x+v2.y*wb2.y+v2.z*wb2.z+v2.w*wb2.w
                          + v3.x*wb3.x+v3.y*wb3.y+v3.z*wb3.z+v3.w*wb3.w;
                }
            }
            #pragma unroll
            for (int r = 0; r < 8; r++) {
                #pragma unroll
                for (int o = 16; o; o >>= 1) {
                    p0[r] += __shfl_xor_sync(~0u, p0[r], o);
                    p1[r] += __shfl_xor_sync(~0u, p1[r], o);
                }
            }
            asm volatile("cp.async.wait_group 0;\n" ::: "memory");
            if (lane < 8) {
                float a0=0.f, a1=0.f;
                #pragma unroll
                for (int r = 0; r < 8; r++) if (lane == r) { a0 = p0[r]; a1 = p1[r]; }
                int rr = rbase + lane;
                float fl0 = a0 + sFX[rr*2], fl1 = a1 + sFX[rr*2+1];
                float h0 = tanhf(sMLP[0]*fl0 + sMLP[1]*fl1 + sMLP[8]);
                float h1 = tanhf(sMLP[2]*fl0 + sMLP[3]*fl1 + sMLP[9]);
                float h2 = tanhf(sMLP[4]*fl0 + sMLP[5]*fl1 + sMLP[10]);
                float h3 = tanhf(sMLP[6]*fl0 + sMLP[7]*fl1 + sMLP[11]);
                float dl = sMLP[12]*h0 + sMLP[13]*h1 + sMLP[14]*h2 + sMLP[15]*h3 + sMLP[16];
                sF[rr] = sigm(dl);
            }
        }
        __syncthreads();

        // epilogue: sum 4 K-quarter partials + x-part (from smem) + bias; LSTM update
        asm volatile("cp.async.wait_group 0;\n" ::: "memory");
        float gi = sGX[tid], gu = sGX[512+tid], go = sGX[1024+tid];
        float fv = sF[rp];
        float pi = sO[(  rp)*LDO + jp]      + sO[(32+rp)*LDO + jp]
                 + sO[(64+rp)*LDO + jp]     + sO[(96+rp)*LDO + jp]      + gi + sB[jp];
        float pu = sO[(  rp)*LDO + 16+jp]   + sO[(32+rp)*LDO + 16+jp]
                 + sO[(64+rp)*LDO + 16+jp]  + sO[(96+rp)*LDO + 16+jp]   + gu + sB[16+jp];
        float po = sO[(  rp)*LDO + 32+jp]   + sO[(32+rp)*LDO + 32+jp]
                 + sO[(64+rp)*LDO + 32+jp]  + sO[(96+rp)*LDO + 32+jp]   + go + sB[32+jp];
        cst = fv*cst + sigm(pi)*tanhf(pu);
        float hv = sigm(po)*tanhf(cst);
        out[(size_t)t*BH_ + (size_t)bq*H + jj] = hv;
        if (t == TS-1 && tail) {
            out[TBH_ + (size_t)bq*H + jj] = hv;
            out[TBH_ + BH_ + (size_t)bq*H + jj] = cst;
        }
        __syncthreads();
        if (tid == 0) {
            __threadfence();
            *(volatile unsigned*)&g_flagw[(size_t)t*NGC + blockIdx.x] = 1u;
        }
    }
}

extern "C" void kernel_launch(void* const* d_in, const int* in_sizes, int n_in,
                              void* d_out, int out_size) {
    const float* X   = (const float*)d_in[0];
    const float* Wf  = (const float*)d_in[1];
    const float* bf  = (const float*)d_in[2];
    const float* Wi  = (const float*)d_in[3];
    const float* bi  = (const float*)d_in[4];
    const float* Wu  = (const float*)d_in[5];
    const float* bu  = (const float*)d_in[6];
    const float* Wo  = (const float*)d_in[7];
    const float* bo  = (const float*)d_in[8];
    const float* Ws1 = (const float*)d_in[9];
    const float* bs1 = (const float*)d_in[10];
    const float* Ws2 = (const float*)d_in[11];
    const float* bs2 = (const float*)d_in[12];
    float* out = (float*)d_out;

    cudaFuncSetAttribute(rec_kernel, cudaFuncAttributeMaxDynamicSharedMemorySize, REC_SMEM);
    cudaFuncSetAttribute(gemm_x,     cudaFuncAttributeMaxDynamicSharedMemorySize, GX_SMEM);

    prep_kernel<<<NG3+8, 128>>>(Wi, Wu, Wo, bi, bu, bo);
    prepx_kernel<<<MT*D/1024, 256>>>(X);
    fx_kernel<<<MT/8, 256>>>(X, Wf, bf);
    dim3 g(NG3/128, MT/128);
    gemm_x<<<g, 256, GX_SMEM>>>();
    rec_kernel<<<NGC, 512, REC_SMEM>>>(out, Wf, Ws1, bs1, Ws2, bs2, (long long)out_size);
}